// round 11
// baseline (speedup 1.0000x reference)
#include <cuda_runtime.h>
#include <cuda_bf16.h>
#include <math.h>

#define M_TOTAL 184320
#define ORTHO_F (1.0f/256.0f)

typedef unsigned int u32;
typedef unsigned long long u64;

// ---- static device scratch (small, proven sizes only) ----
__device__ float2 g_kdc[M_TOTAL];                      // blended kdc (fwd output)
__device__ __align__(16) u32 g_Bh[256*512];            // expanded image bf16-hi
__device__ __align__(16) u32 g_Bl[256*512];            // bf16-lo residual

__device__ __forceinline__ float2 cmulf(float2 a, float2 b){
    return make_float2(fmaf(a.x,b.x,-(a.y*b.y)), fmaf(a.x,b.y,a.y*b.x));
}
__device__ __forceinline__ u32 bf2pack(float x, float y){
    u32 r; asm("cvt.rn.bf16x2.f32 %0, %1, %2;" : "=r"(r) : "f"(y), "f"(x)); return r;
}
__device__ __forceinline__ void csplit(float x, float y, u32 &h32, u32 &l32){
    h32 = bf2pack(x, y);
    float hx = __uint_as_float(h32 << 16);
    float hy = __uint_as_float(h32 & 0xFFFF0000u);
    l32 = bf2pack(x - hx, y - hy);
}

#define MMA(c, a0,a1,a2,a3, b0,b1) \
    asm volatile("mma.sync.aligned.m16n8k16.row.col.f32.bf16.bf16.f32 " \
        "{%0,%1,%2,%3}, {%4,%5,%6,%7}, {%8,%9}, {%0,%1,%2,%3};" \
        : "+f"((c)[0]), "+f"((c)[1]), "+f"((c)[2]), "+f"((c)[3]) \
        : "r"(a0), "r"(a1), "r"(a2), "r"(a3), "r"(b0), "r"(b1))

__device__ __forceinline__ void cpa16p(u32* dst, const u32* src){
    u32 d = (u32)__cvta_generic_to_shared(dst);
    asm volatile("cp.async.cg.shared.global [%0], [%1], 16;" :: "r"(d), "l"(src));
}
#define CP_COMMIT() asm volatile("cp.async.commit_group;")
#define CP_WAIT(n)  asm volatile("cp.async.wait_group %0;" :: "n"(n) : "memory")

#define AST 12
#define BST 520
#define ABUF (64*AST)
#define BBUF (8*BST)

// ============================================================================
// Prep: expand fp32 image -> split-bf16 real-GEMM B layout.
// Row u, col 2w = (r, -i), col 2w+1 = (i, r).
// ============================================================================
__global__ void prep_kernel(const float* __restrict__ img){
    int idx = blockIdx.x*256 + threadIdx.x;       // 65536
    float2 p = ((const float2*)img)[idx];
    int u = idx >> 8, w = idx & 255;
    u32 h32, l32; csplit(p.x, p.y, h32, l32);
    g_Bh[u*512 + 2*w    ] = h32 ^ 0x80000000u;
    g_Bh[u*512 + 2*w + 1] = __byte_perm(h32, h32, 0x1032);
    g_Bl[u*512 + 2*w    ] = l32 ^ 0x80000000u;
    g_Bl[u*512 + 2*w + 1] = __byte_perm(l32, l32, 0x1032);
}

// ============================================================================
// Forward: R4-PROVEN kernel, verbatim (rel_err 3.8e-5 config).
// Block 64 m x 512 n', 512 threads (16 warps = 4 mw x 4 nw).
// A triple-buffer gen (sincos reseed/step), B double-buffer cp.async.
// Epilogue: Ey-reduce + DC blend -> g_kdc.
// ============================================================================
#define F_SMEM ((6*ABUF + 4*BBUF + 512) * 4)

__global__ __launch_bounds__(512, 1) void fwd_kernel(
    const float* __restrict__ y_radial,
    const float* __restrict__ lambda_p,
    const float* __restrict__ ktraj)
{
    extern __shared__ u32 dyn[];
    u32* sA = dyn;                     // 6*ABUF (3 bufs x hi/lo)
    u32* sB = dyn + 6*ABUF;            // 4*BBUF (2 bufs x hi/lo)
    float2* sEpi = (float2*)(dyn + 6*ABUF + 4*BBUF);   // [64][4]

    const int tid  = threadIdx.x;
    const int lane = tid & 31;
    const int warp = tid >> 5;
    const int mw = warp >> 2, nw = warp & 3;
    const int g = lane >> 2, tig = lane & 3;
    const int mbase = blockIdx.x * 64;

    float acc[16][4];
    #pragma unroll
    for (int nt = 0; nt < 16; nt++)
        #pragma unroll
        for (int c = 0; c < 4; c++) acc[nt][c] = 0.f;

    float kxA = 0.f; float2 wxA = make_float2(1.f, 0.f);
    if (tid < 64){
        kxA = ktraj[mbase + tid];
        float s, c; sincosf(kxA, &s, &c);
        wxA = make_float2(c, -s);              // e^{-i kx}
    }

    #define GEN_A(ab, sg) do{ \
        if (tid < 64){ \
            float ang = kxA * (float)(128 - (sg)*8); \
            float2 cur; sincosf(ang, &cur.y, &cur.x); \
            u32* ah_ = sA + (ab)*2*ABUF; u32* al_ = ah_ + ABUF; \
            _Pragma("unroll") \
            for (int i_ = 0; i_ < 8; i_++){ \
                u32 h_, l_; csplit(cur.x, cur.y, h_, l_); \
                ah_[tid*AST + i_] = h_; al_[tid*AST + i_] = l_; \
                cur = cmulf(cur, wxA); \
            } \
        } \
    } while(0)

    #define COPY_B(bb, sg) do{ \
        u32* bh_ = sB + (bb)*2*BBUF; u32* bl_ = bh_ + BBUF; \
        int u0_ = (sg)*8; \
        _Pragma("unroll") \
        for (int p_ = 0; p_ < 2; p_++){ \
            int seg_ = tid + p_*512; \
            int r_ = seg_ >> 7, si_ = (seg_ & 127)*4; \
            cpa16p(bh_ + r_*BST + si_, g_Bh + (u0_ + r_)*512 + si_); \
            cpa16p(bl_ + r_*BST + si_, g_Bl + (u0_ + r_)*512 + si_); \
        } \
        CP_COMMIT(); \
    } while(0)

    COPY_B(0, 0);
    GEN_A(0, 0);

    for (int s = 0; s < 32; s++){
        if (s < 31) GEN_A((s+1)%3, s+1);
        __syncthreads();
        if (s < 31){ COPY_B((s+1)&1, s+1); CP_WAIT(1); }
        else        CP_WAIT(0);

        const u32* ah = sA + (s%3)*2*ABUF; const u32* al = ah + ABUF;
        const u32* bh = sB + (s&1)*2*BBUF; const u32* bl = bh + BBUF;

        const int m0 = mw*16;
        u32 ah0 = ah[(m0+g)*AST + tig],   ah1 = ah[(m0+g+8)*AST + tig];
        u32 ah2 = ah[(m0+g)*AST + tig+4], ah3 = ah[(m0+g+8)*AST + tig+4];
        u32 al0 = al[(m0+g)*AST + tig],   al1 = al[(m0+g+8)*AST + tig];
        u32 al2 = al[(m0+g)*AST + tig+4], al3 = al[(m0+g+8)*AST + tig+4];
        #pragma unroll
        for (int nt = 0; nt < 16; nt++){
            int col = nw*128 + nt*8 + g;
            u32 bh0 = bh[ tig   *BST + col], bh1 = bh[(tig+4)*BST + col];
            u32 bl0 = bl[ tig   *BST + col], bl1 = bl[(tig+4)*BST + col];
            MMA(acc[nt], ah0, ah1, ah2, ah3, bh0, bh1);
            MMA(acc[nt], ah0, ah1, ah2, ah3, bl0, bl1);
            MMA(acc[nt], al0, al1, al2, al3, bh0, bh1);
        }
    }
    #undef GEN_A
    #undef COPY_B

    // ---- Epilogue: A_m = ORTHO * sum_w C[m,w]*Ey[m,w], DC blend ----
    #pragma unroll
    for (int r = 0; r < 2; r++){
        int ml = mw*16 + g + 8*r;
        int m  = mbase + ml;
        float ky = ktraj[M_TOTAL + m];
        int w0 = nw*64 + tig;
        float2 e, st;
        { float s_, c_; sincosf(-ky * (float)(w0 - 128), &s_, &c_); e  = make_float2(c_, s_); }
        { float s_, c_; sincosf(-4.f * ky,               &s_, &c_); st = make_float2(c_, s_); }
        float2 part = make_float2(0.f, 0.f);
        #pragma unroll
        for (int nt = 0; nt < 16; nt++){
            float cr = acc[nt][2*r], ci = acc[nt][2*r + 1];
            part.x += cr*e.x - ci*e.y;
            part.y += cr*e.y + ci*e.x;
            e = cmulf(e, st);
        }
        part.x += __shfl_xor_sync(0xffffffffu, part.x, 1);
        part.y += __shfl_xor_sync(0xffffffffu, part.y, 1);
        part.x += __shfl_xor_sync(0xffffffffu, part.x, 2);
        part.y += __shfl_xor_sync(0xffffffffu, part.y, 2);
        if (tig == 0) sEpi[ml*4 + nw] = part;
    }
    __syncthreads();

    if (tid < 64){
        float2 s0 = sEpi[tid*4 + 0];
        s0.x += sEpi[tid*4+1].x + sEpi[tid*4+2].x + sEpi[tid*4+3].x;
        s0.y += sEpi[tid*4+1].y + sEpi[tid*4+2].y + sEpi[tid*4+3].y;
        int m = mbase + tid;
        float kx = ktraj[m], ky = ktraj[M_TOTAL + m];
        float lam = 1.f / (1.f + expf(-lambda_p[0]));
        float dcf = sqrtf(kx*kx + ky*ky);
        float ar = s0.x * ORTHO_F, ai = s0.y * ORTHO_F;
        int tt = m % 640, ss = m / 640;
        const float* yp = y_radial + ((size_t)tt*288 + ss)*2;
        float2 kd;
        kd.x = lam*dcf*ar + (1.f - lam)*yp[0];
        kd.y = lam*dcf*ai + (1.f - lam)*yp[1];
        g_kdc[m] = kd;
    }
}

// ============================================================================
// Adjoint: R9's proven structure, halved to 2 blocks/SM for gen/MMA overlap.
// Block 64 u x 256 n' (vblk splits n'), 256 threads (8 warps = 4 uw x 2 nw).
// Steps of 8 m, triple-buffered gen before sync, 1 sync/step.
// Grid: 36 chunks x 4 ublk x 2 vblk = 288 blocks = 2/SM x 144 SMs.
// ============================================================================
#define BST2 264
#define BBUF2 (8*BST2)
#define ADJ_MS 5120
#define ADJ_STEPS (ADJ_MS/8)
#define A_SMEM ((6*ABUF + 6*BBUF2) * 4)    // 69120 B

__global__ __launch_bounds__(256, 2) void adj_kernel(
    const float* __restrict__ ktraj,
    float* __restrict__ out)
{
    extern __shared__ u32 dyn[];
    u32* sA = dyn;                 // 6*ABUF (3 bufs x hi/lo)
    u32* sB = dyn + 6*ABUF;        // 6*BBUF2 (3 bufs x hi/lo)

    const int tid  = threadIdx.x;
    const int lane = tid & 31;
    const int warp = tid >> 5;
    const int uw = warp >> 1, nw = warp & 1;
    const int g = lane >> 2, tig = lane & 3;
    const int m0base = blockIdx.x * ADJ_MS;
    const int ublk = blockIdx.y, vblk = blockIdx.z;

    float acc[16][4];
    #pragma unroll
    for (int nt = 0; nt < 16; nt++)
        #pragma unroll
        for (int c = 0; c < 4; c++) acc[nt][c] = 0.f;

    // gen roles: A: 2 entries (u = au, au+32) x m-col aml; B: 4 v x m-row bml
    const int aml = tid & 7,  au = tid >> 3;       // au 0..31
    const int bml = tid >> 5, bv0 = tid & 31;      // bml 0..7, v_local = bv0+32i
    const float uc0 = (float)(ublk*64 + au - 128);
    const float uc1 = uc0 + 32.f;
    const float vc0 = (float)(vblk*128 + bv0 - 128);

    float kx_p  = ktraj[m0base + aml];
    float ky_p  = ktraj[M_TOTAL + m0base + bml];
    float2 kd_p = g_kdc[m0base + bml];

    #define GEN_STEP(ab, sg) do{ \
        /* A: two entries (direct sincos each) */ \
        { u32* ah_ = sA + (ab)*2*ABUF; u32* al_ = ah_ + ABUF; \
          float2 e_; sincosf(kx_p * uc0, &e_.y, &e_.x); \
          u32 h_, l_; csplit(e_.x, e_.y, h_, l_); \
          ah_[au*AST + aml] = h_; al_[au*AST + aml] = l_; \
          sincosf(kx_p * uc1, &e_.y, &e_.x); \
          csplit(e_.x, e_.y, h_, l_); \
          ah_[(au+32)*AST + aml] = h_; al_[(au+32)*AST + aml] = l_; } \
        /* B: 4 entries, v_local strided by 32 */ \
        { float2 kd_ = make_float2(kd_p.x*ORTHO_F, kd_p.y*ORTHO_F); \
          float2 e_; sincosf(ky_p * vc0, &e_.y, &e_.x); \
          float2 bb_ = cmulf(kd_, e_); \
          float2 w32_; sincosf(ky_p * 32.f, &w32_.y, &w32_.x); \
          u32* bh_ = sB + (ab)*2*BBUF2; u32* bl_ = bh_ + BBUF2; \
          _Pragma("unroll") \
          for (int i_ = 0; i_ < 4; i_++){ \
            int v_ = bv0 + 32*i_; \
            u32 h_, l_; csplit(bb_.x, bb_.y, h_, l_); \
            u64 hv_ = (u64)(h_ ^ 0x80000000u) | ((u64)__byte_perm(h_, h_, 0x1032) << 32); \
            *(u64*)&bh_[bml*BST2 + 2*v_] = hv_; \
            u64 lv_ = (u64)(l_ ^ 0x80000000u) | ((u64)__byte_perm(l_, l_, 0x1032) << 32); \
            *(u64*)&bl_[bml*BST2 + 2*v_] = lv_; \
            bb_ = cmulf(bb_, w32_); \
          } } \
        /* prefetch next step params */ \
        if ((sg) + 1 < ADJ_STEPS){ \
            int mn_ = m0base + ((sg)+1)*8; \
            kx_p = ktraj[mn_ + aml]; \
            ky_p = ktraj[M_TOTAL + mn_ + bml]; \
            kd_p = g_kdc[mn_ + bml]; \
        } \
    } while(0)

    GEN_STEP(0, 0);

    for (int s = 0; s < ADJ_STEPS; s++){
        if (s + 1 < ADJ_STEPS) GEN_STEP((s+1)%3, s+1);
        __syncthreads();

        const u32* ah = sA + (s%3)*2*ABUF; const u32* al = ah + ABUF;
        const u32* bh = sB + (s%3)*2*BBUF2; const u32* bl = bh + BBUF2;

        const int u0 = uw*16;
        u32 ah0 = ah[(u0+g)*AST + tig],   ah1 = ah[(u0+g+8)*AST + tig];
        u32 ah2 = ah[(u0+g)*AST + tig+4], ah3 = ah[(u0+g+8)*AST + tig+4];
        u32 al0 = al[(u0+g)*AST + tig],   al1 = al[(u0+g+8)*AST + tig];
        u32 al2 = al[(u0+g)*AST + tig+4], al3 = al[(u0+g+8)*AST + tig+4];
        #pragma unroll
        for (int nt = 0; nt < 16; nt++){
            int col = nw*128 + nt*8 + g;
            u32 bh0 = bh[ tig   *BST2 + col], bh1 = bh[(tig+4)*BST2 + col];
            u32 bl0 = bl[ tig   *BST2 + col], bl1 = bl[(tig+4)*BST2 + col];
            MMA(acc[nt], ah0, ah1, ah2, ah3, bh0, bh1);
            MMA(acc[nt], ah0, ah1, ah2, ah3, bl0, bl1);
            MMA(acc[nt], al0, al1, al2, al3, bh0, bh1);
        }
    }
    #undef GEN_STEP

    // ---- split-K accumulate ----
    #pragma unroll
    for (int nt = 0; nt < 16; nt++){
        int np = vblk*256 + nw*128 + nt*8 + 2*tig;
        int r0 = ublk*64 + uw*16 + g;
        float* p0 = out + (size_t)r0*512 + np;
        float* p1 = out + (size_t)(r0+8)*512 + np;
        atomicAdd(p0,     acc[nt][0]);
        atomicAdd(p0 + 1, acc[nt][1]);
        atomicAdd(p1,     acc[nt][2]);
        atomicAdd(p1 + 1, acc[nt][3]);
    }
}

extern "C" void kernel_launch(void* const* d_in, const int* in_sizes, int n_in,
                              void* d_out, int out_size)
{
    const float* x   = (const float*)d_in[0];  // (1,1,256,256,2)
    const float* y   = (const float*)d_in[1];  // (640,288,2)
    const float* lp  = (const float*)d_in[2];  // (1,)
    const float* kt  = (const float*)d_in[3];  // (1,2,184320)
    float* out = (float*)d_out;                // (1,1,256,256,2)

    cudaFuncSetAttribute(fwd_kernel, cudaFuncAttributeMaxDynamicSharedMemorySize, F_SMEM);
    cudaFuncSetAttribute(adj_kernel, cudaFuncAttributeMaxDynamicSharedMemorySize, A_SMEM);

    cudaMemsetAsync(d_out, 0, (size_t)out_size * sizeof(float), 0);
    prep_kernel<<<256, 256>>>(x);
    fwd_kernel<<<M_TOTAL/64, 512, F_SMEM>>>(y, lp, kt);
    adj_kernel<<<dim3(36, 4, 2), 256, A_SMEM>>>(kt, out);
}